// round 3
// baseline (speedup 1.0000x reference)
#include <cuda_runtime.h>
#include <math.h>

// BayesRingRNN collapses exactly to a 2-scalar recurrence per batch:
// r_i(t) = u(t)*cos(phi_i) + v(t)*sin(phi_i)   (rank-2 weights, r0 in span).
//
// Fused producer/consumer kernel:
//   - CTAs [0,128): warp-per-batch serial chain -> g_traj, publish per-chunk flag
//   - ALL CTAs: bandwidth-bound expansion to (B,T,N), gated per chunk on the flag
// Chain produces a 32-step chunk every ~0.6us; expansion consumes one every
// ~1.7us -> expansion never stalls after chunk 0; makespan == expansion time.

#define NN 80
#define TT 1500
#define MAXB 1024
#define CH 32
#define NCHUNK ((TT + CH - 1) / CH)   // 47

__device__ float2 g_traj[(size_t)MAXB * TT];   // 12.3 MB (L2-resident)
__device__ int    g_cnt[NCHUNK];               // chunk-complete counters (memset per launch)

__device__ __forceinline__ int ld_acq(const int* p) {
    int v;
    asm volatile("ld.acquire.gpu.b32 %0, [%1];" : "=r"(v) : "l"(p));
    return v;
}

template <int LC>
__device__ __forceinline__ void expand_chunk(
    int c, int B, int gtid, int gsz,
    const float4* __restrict__ c4, const float4* __restrict__ s4,
    float4* __restrict__ o4)
{
    const int t0 = c * CH;
    const int Ec = B * LC * (NN / 4);
    for (int l = gtid; l < Ec; l += gsz) {
        const int q  = l / 20;              // const-divisor mul-shift
        const int n4 = l - q * 20;
        const int b  = q / LC;              // LC is a literal (32 or 28)
        const int tt = q - b * LC;
        const float2 uv = g_traj[b * TT + t0 + tt];
        const float4 cc = c4[n4];
        const float4 ss = s4[n4];
        float4 o;
        o.x = fmaf(uv.y, ss.x, uv.x * cc.x);
        o.y = fmaf(uv.y, ss.y, uv.x * cc.y);
        o.z = fmaf(uv.y, ss.z, uv.x * cc.z);
        o.w = fmaf(uv.y, ss.w, uv.x * cc.w);
        __stcs(&o4[(b * TT + t0 + tt) * 20 + n4], o);   // streaming store
    }
}

__global__ void __launch_bounds__(256, 6)
fused_kernel(const float* __restrict__ inputs,   // (B,T,2)
             const float* __restrict__ phi,      // (N,)
             float* __restrict__ out,            // (B,T,N) then (1,B,N)
             int B, float kz, long long out_size)
{
    __shared__ float4 c4[NN / 4], s4[NN / 4];
    if (threadIdx.x < NN) {
        float s, c; sincosf(phi[threadIdx.x], &s, &c);
        reinterpret_cast<float*>(c4)[threadIdx.x] = c;
        reinterpret_cast<float*>(s4)[threadIdx.x] = s;
    }
    __syncthreads();

    const int lane = threadIdx.x & 31;
    const int nChainCTAs = (B + 7) / 8;

    // ------------------------------------------------------------- producer
    if (blockIdx.x < nChainCTAs) {
        const int b = blockIdx.x * 8 + (threadIdx.x >> 5);
        if (b < B) {
            const float C1 = 0.01f / 3.0f;   // DT/(KP+KV)
            const float C3 = 2.0f / 3.0f;    // a_odd
            // (1 - ALPHA*DT) + DT*a_even == 1 exactly (terms cancel)
            float u = 10.0f, v = 0.0f;       // r0 = 10*cos(phi)

            const float2* inp = reinterpret_cast<const float2*>(inputs) + (size_t)b * TT;
            float2* tr = g_traj + (size_t)b * TT;

            for (int c = 0; c < NCHUNK; ++c) {
                const int t = c * CH;
                const int chunk = min(CH, TT - t);
                float kc = 0.f, ks = 0.f, gi = 0.f;
                if (lane < chunk) {
                    float2 x = inp[t + lane];
                    float s, co; sincosf(x.x, &s, &co);
                    kc = kz * co; ks = kz * s; gi = C3 * x.y;
                }
                float su = u, sv = v;
                #pragma unroll 4
                for (int j = 0; j < chunk; ++j) {
                    const float gij = __shfl_sync(0xffffffffu, gi, j);
                    const float kcj = __shfl_sync(0xffffffffu, kc, j);
                    const float ksj = __shfl_sync(0xffffffffu, ks, j);

                    const float x = fmaf(u, u, v * v);       // |z|^2 > 0 always
                    const float y = rsqrtf(x);               // MUFU.RSQ
                    const float d = fmaf(-(C1 * x), y, 1.0f);
                    const float nu = fmaf(d, u, fmaf(-gij, v, kcj));
                    const float nv = fmaf(d, v, fmaf( gij, u, ksj));
                    u = nu; v = nv;
                    if (j == lane) { su = u; sv = v; }
                }
                if (lane < chunk) tr[t + lane] = make_float2(su, sv);
                __syncwarp();                 // warp-scope fence: all lanes' stores
                __threadfence();              // publish to gpu scope
                if (lane == 0) atomicAdd(&g_cnt[c], 1);
            }

            // r_final (1,B,N) after the (B,T,N) block
            const long long base = (long long)B * TT * NN;
            if (out_size >= base + (long long)B * NN) {
                float* fp = out + base + (size_t)b * NN;
                const float* cs = reinterpret_cast<const float*>(c4);
                const float* sn = reinterpret_cast<const float*>(s4);
                fp[lane]      = fmaf(v, sn[lane],      u * cs[lane]);
                fp[lane + 32] = fmaf(v, sn[lane + 32], u * cs[lane + 32]);
                if (lane < NN - 64)
                    fp[lane + 64] = fmaf(v, sn[lane + 64], u * cs[lane + 64]);
            }
        }
    }

    // ------------------------------------------------------------- consumer
    const int gsz  = gridDim.x * blockDim.x;
    const int gtid = blockIdx.x * blockDim.x + threadIdx.x;
    float4* o4 = reinterpret_cast<float4*>(out);

    #pragma unroll 1
    for (int c = 0; c < NCHUNK - 1; ++c) {          // full 32-step chunks
        if (lane == 0) {
            while (ld_acq(&g_cnt[c]) < B) __nanosleep(64);
        }
        __syncwarp();
        expand_chunk<CH>(c, B, gtid, gsz, c4, s4, o4);
    }
    {                                               // last chunk: 28 steps
        const int c = NCHUNK - 1;
        if (lane == 0) {
            while (ld_acq(&g_cnt[c]) < B) __nanosleep(64);
        }
        __syncwarp();
        expand_chunk<TT - (NCHUNK - 1) * CH>(c, B, gtid, gsz, c4, s4, o4);
    }
}

// --- host-side exact replica of the reference's _xi_inv (double precision) --
static double xi_f(double a, double target)
{
    const double x = (a / 2.0) * (a / 2.0);
    double t0 = 1.0, t1 = a / 2.0;
    double i0 = t0, i1 = t1;
    for (int k = 1; k < 30; ++k) {
        t0 *= x / ((double)k * (double)k);
        t1 *= x / ((double)k * (double)(k + 1));
        i0 += t0;
        i1 += t1;
    }
    return a * i1 / i0 - target;
}

static float compute_kappa_z()
{
    const double target = 15.0 * 0.01;
    double lo = 1e-3, hi = 50.0;
    for (int i = 0; i < 200; ++i) {
        const double mid = 0.5 * (lo + hi);
        if (xi_f(lo, target) * xi_f(mid, target) <= 0.0) hi = mid;
        else lo = mid;
    }
    return (float)(0.5 * (lo + hi));
}

extern "C" void kernel_launch(void* const* d_in, const int* in_sizes, int n_in,
                              void* d_out, int out_size)
{
    const float* inputs = (const float*)d_in[0];  // (B,T,2)
    const float* phi    = (const float*)d_in[4];  // (N,)
    float* out = (float*)d_out;

    int B = in_sizes[0] / (2 * TT);
    if (B > MAXB) B = MAXB;
    const float kz = compute_kappa_z();

    // reset chunk counters (memset node in the graph, no allocation)
    void* cnt_ptr = nullptr;
    cudaGetSymbolAddress(&cnt_ptr, g_cnt);
    cudaMemsetAsync(cnt_ptr, 0, sizeof(int) * NCHUNK);

    const int threads = 256;
    const int blocks  = 888;   // 6 CTAs/SM x 148 SMs, all co-resident
    fused_kernel<<<blocks, threads>>>(inputs, phi, out, B, kz, (long long)out_size);
}

// round 4
// speedup vs baseline: 6.9756x; 6.9756x over previous
#include <cuda_runtime.h>
#include <math.h>

// BayesRingRNN collapses exactly to a 2-scalar recurrence per batch:
// r_i(t) = u(t)*cos(phi_i) + v(t)*sin(phi_i)   (rank-2 weights, r0 in span).
//
// One warp per batch. Serial recurrence on all lanes (redundant); lanes 0..19
// each own 4 neurons and emit one STG.128 per timestep -> warp writes one
// contiguous 320B row per step. rsqrtf keeps the serial path ~28 cycles so
// 1024 warps over-offer stores and the kernel is HBM-write-bound.

#define NN 80
#define TT 1500

__global__ void __launch_bounds__(128, 8)
ring_kernel(const float* __restrict__ inputs,   // (B,T,2)
            const float* __restrict__ phi,      // (N,)
            float* __restrict__ out,            // (B,T,N) then (1,B,N)
            int B, float kz, long long out_size)
{
    const int b    = (blockIdx.x * blockDim.x + threadIdx.x) >> 5;
    const int lane = threadIdx.x & 31;
    if (b >= B) return;

    // Per-lane neuron basis: lanes 0..19 hold cos/sin for neurons 4l..4l+3
    float4 c4 = make_float4(0.f, 0.f, 0.f, 0.f);
    float4 s4 = make_float4(0.f, 0.f, 0.f, 0.f);
    if (lane < NN / 4) {
        sincosf(phi[4 * lane + 0], &s4.x, &c4.x);
        sincosf(phi[4 * lane + 1], &s4.y, &c4.y);
        sincosf(phi[4 * lane + 2], &s4.z, &c4.z);
        sincosf(phi[4 * lane + 3], &s4.w, &c4.w);
    }

    // KP=1, KV=2, DT=0.01. The -ALPHA*DT*r and +DT*a_even*(W_even r) terms
    // cancel exactly in (u,v) space, leaving: coeff = 1 - (DT/3)*|z|.
    const float C1 = 0.01f / 3.0f;   // DT/(KP+KV)
    const float C3 = 2.0f / 3.0f;    // a_odd

    float u = 10.0f;   // r0 = 10*cos(phi) -> (u,v)=(10,0) exactly
    float v = 0.0f;

    const float2* __restrict__ inp = reinterpret_cast<const float2*>(inputs) + (size_t)b * TT;
    float4* __restrict__ o4 = reinterpret_cast<float4*>(out) + (size_t)b * TT * (NN / 4) + lane;

    float2 nx = inp[lane];   // prefetch chunk 0

    for (int t = 0; t < TT; t += 32) {
        const int chunk = min(32, TT - t);
        const float2 x = nx;
        if (t + 32 + lane < TT) nx = inp[t + 32 + lane];   // prefetch next chunk

        float kc = 0.f, ks = 0.f, gi = 0.f;
        if (lane < chunk) {
            float s, c; sincosf(x.x, &s, &c);
            kc = kz * c; ks = kz * s; gi = C3 * x.y;
        }

        #pragma unroll 4
        for (int j = 0; j < chunk; ++j) {
            const float gij = __shfl_sync(0xffffffffu, gi, j);
            const float kcj = __shfl_sync(0xffffffffu, kc, j);
            const float ksj = __shfl_sync(0xffffffffu, ks, j);

            const float xx = fmaf(u, u, v * v);        // |z|^2 > 0 always
            const float y  = rsqrtf(xx);               // MUFU.RSQ
            const float d  = fmaf(-(C1 * xx), y, 1.0f);
            const float nu = fmaf(d, u, fmaf(-gij, v, kcj));
            const float nv = fmaf(d, v, fmaf( gij, u, ksj));
            u = nu; v = nv;

            if (lane < NN / 4) {
                float4 o;
                o.x = fmaf(v, s4.x, u * c4.x);
                o.y = fmaf(v, s4.y, u * c4.y);
                o.z = fmaf(v, s4.z, u * c4.z);
                o.w = fmaf(v, s4.w, u * c4.w);
                *o4 = o;                               // one STG.128 per step
            }
            o4 += NN / 4;
        }
    }

    // r_final (1,B,N) appended after the (B,T,N) block
    const long long base = (long long)B * TT * NN;
    if (out_size >= base + (long long)B * NN && lane < NN / 4) {
        float4* fp = reinterpret_cast<float4*>(out + base + (size_t)b * NN) + lane;
        float4 o;
        o.x = fmaf(v, s4.x, u * c4.x);
        o.y = fmaf(v, s4.y, u * c4.y);
        o.z = fmaf(v, s4.z, u * c4.z);
        o.w = fmaf(v, s4.w, u * c4.w);
        *fp = o;
    }
}

// --- host-side exact replica of the reference's _xi_inv (double precision) --
static double xi_f(double a, double target)
{
    const double x = (a / 2.0) * (a / 2.0);
    double t0 = 1.0, t1 = a / 2.0;
    double i0 = t0, i1 = t1;
    for (int k = 1; k < 30; ++k) {
        t0 *= x / ((double)k * (double)k);
        t1 *= x / ((double)k * (double)(k + 1));
        i0 += t0;
        i1 += t1;
    }
    return a * i1 / i0 - target;
}

static float compute_kappa_z()
{
    const double target = 15.0 * 0.01;
    double lo = 1e-3, hi = 50.0;
    for (int i = 0; i < 200; ++i) {
        const double mid = 0.5 * (lo + hi);
        if (xi_f(lo, target) * xi_f(mid, target) <= 0.0) hi = mid;
        else lo = mid;
    }
    return (float)(0.5 * (lo + hi));
}

extern "C" void kernel_launch(void* const* d_in, const int* in_sizes, int n_in,
                              void* d_out, int out_size)
{
    const float* inputs = (const float*)d_in[0];  // (B,T,2)
    const float* phi    = (const float*)d_in[4];  // (N,)
    float* out = (float*)d_out;

    const int B = in_sizes[0] / (2 * TT);
    const float kz = compute_kappa_z();

    const int threads = 128;                    // 4 warps = 4 batches per block
    const int blocks = (B * 32 + threads - 1) / threads;
    ring_kernel<<<blocks, threads>>>(inputs, phi, out, B, kz, (long long)out_size);
}

// round 5
// speedup vs baseline: 7.4683x; 1.0706x over previous
#include <cuda_runtime.h>
#include <math.h>

// BayesRingRNN collapses exactly to a 2-scalar recurrence per batch:
// r_i(t) = u(t)*cos(phi_i) + v(t)*sin(phi_i)   (rank-2 weights, r0 in span).
//
// CTA-local producer/consumer: warps 0-3 run the serial (u,v) chains for 4
// batches and publish 32-step chunks into an 8-deep smem ring; warps 4-7
// expand chunks to (B,T,N) with full store MLP. All sync is smem-local
// (volatile flags + named barrier) -- zero cross-CTA traffic.

#define NN 80
#define TT 1500
#define CH 32
#define NCHUNK ((TT + CH - 1) / CH)   // 47 (last chunk = 28 steps)
#define NBUF 8

__device__ __forceinline__ void nsleep(unsigned ns) { __nanosleep(ns); }

template <int LC>
__device__ __forceinline__ void expand_chunk(
    int c, int buf, int nb, int tid2,
    const float2 (*uv)[NBUF][CH],
    const float4* __restrict__ c4, const float4* __restrict__ s4,
    float4* __restrict__ o4base)
{
    const int total = nb * LC * 20;
    #pragma unroll 4
    for (int l = tid2; l < total; l += 128) {
        const int q    = l / 20;            // bl*LC + step (const-div mul-shift)
        const int n4   = l - q * 20;
        const int bl   = q / LC;            // LC literal
        const int step = q - bl * LC;
        const float2 z = uv[bl][buf][step];
        const float4 cc = c4[n4];
        const float4 ss = s4[n4];
        float4 o;
        o.x = fmaf(z.y, ss.x, z.x * cc.x);
        o.y = fmaf(z.y, ss.y, z.x * cc.y);
        o.z = fmaf(z.y, ss.z, z.x * cc.z);
        o.w = fmaf(z.y, ss.w, z.x * cc.w);
        __stcs(&o4base[((size_t)bl * TT + c * CH + step) * 20 + n4], o);
    }
}

__global__ void __launch_bounds__(256, 4)
ring_kernel(const float* __restrict__ inputs,   // (B,T,2)
            const float* __restrict__ phi,      // (N,)
            float* __restrict__ out,            // (B,T,N) then (1,B,N)
            int B, float kz, long long out_size)
{
    __shared__ float4 c4s[NN / 4], s4s[NN / 4];
    __shared__ float2 uv_sm[4][NBUF][CH];       // 8 KB ring
    __shared__ int    prod_flag[4][NBUF];       // monotone chunk counters
    __shared__ int    cons_done;                // chunks fully consumed

    const int tid  = threadIdx.x;
    const int wid  = tid >> 5;
    const int lane = tid & 31;

    if (tid < NN) {
        float s, c; sincosf(phi[tid], &s, &c);
        reinterpret_cast<float*>(c4s)[tid] = c;
        reinterpret_cast<float*>(s4s)[tid] = s;
    }
    if (tid < 4 * NBUF) reinterpret_cast<int*>(prod_flag)[tid] = 0;
    if (tid == 0) cons_done = 0;
    __syncthreads();

    const int b0 = blockIdx.x * 4;
    const int nb = min(4, B - b0);

    if (wid < 4) {
        // ------------------------------------------------------- producers
        const int b = b0 + wid;
        if (b < B) {
            const float C1 = 0.01f / 3.0f;   // DT/(KP+KV)
            const float C3 = 2.0f / 3.0f;    // a_odd
            float u = 10.0f, v = 0.0f;       // r0 = 10*cos(phi)

            const float2* __restrict__ inp =
                reinterpret_cast<const float2*>(inputs) + (size_t)b * TT;
            float2 nx = inp[lane];           // prefetch chunk 0

            for (int c = 0; c < NCHUNK; ++c) {
                const int t = c * CH;
                const int chunk = (c == NCHUNK - 1) ? (TT - t) : CH;
                const int buf = c & (NBUF - 1);

                // ring backpressure (producer is ~3x faster than consumer)
                if (c >= NBUF && lane == 0) {
                    while (*(volatile int*)&cons_done < c - NBUF + 1) nsleep(100);
                }
                __syncwarp();

                const float2 x = nx;
                if (t + CH + lane < TT) nx = inp[t + CH + lane];

                float kc = 0.f, ks = 0.f, gi = 0.f;
                if (lane < chunk) {
                    float s, co; sincosf(x.x, &s, &co);
                    kc = kz * co; ks = kz * s; gi = C3 * x.y;
                }
                float su = u, sv = v;
                #pragma unroll 4
                for (int j = 0; j < chunk; ++j) {
                    const float gij = __shfl_sync(0xffffffffu, gi, j);
                    const float kcj = __shfl_sync(0xffffffffu, kc, j);
                    const float ksj = __shfl_sync(0xffffffffu, ks, j);

                    const float xx = fmaf(u, u, v * v);   // |z|^2 > 0 always
                    const float y  = rsqrtf(xx);          // MUFU.RSQ
                    const float d  = fmaf(-(C1 * xx), y, 1.0f);
                    const float nu = fmaf(d, u, fmaf(-gij, v, kcj));
                    const float nv = fmaf(d, v, fmaf( gij, u, ksj));
                    u = nu; v = nv;
                    if (j == lane) { su = u; sv = v; }
                }
                if (lane < chunk) uv_sm[wid][buf][lane] = make_float2(su, sv);
                __syncwarp();
                __threadfence_block();
                if (lane == 0) *(volatile int*)&prod_flag[wid][buf] = c + 1;
            }

            // r_final (1,B,N) after the (B,T,N) block
            const long long base = (long long)B * TT * NN;
            if (out_size >= base + (long long)B * NN && lane < NN / 4) {
                const float4 cc = c4s[lane], ss = s4s[lane];
                float4 o;
                o.x = fmaf(v, ss.x, u * cc.x);
                o.y = fmaf(v, ss.y, u * cc.y);
                o.z = fmaf(v, ss.z, u * cc.z);
                o.w = fmaf(v, ss.w, u * cc.w);
                reinterpret_cast<float4*>(out + base + (size_t)b * NN)[lane] = o;
            }
        }
    } else {
        // ------------------------------------------------------- consumers
        const int tid2 = tid - 128;
        float4* __restrict__ o4base =
            reinterpret_cast<float4*>(out) + (size_t)b0 * TT * (NN / 4);

        for (int c = 0; c < NCHUNK; ++c) {
            const int buf = c & (NBUF - 1);
            asm volatile("bar.sync 1, 128;" ::: "memory");  // all done with c-1
            if (tid2 == 0) {
                *(volatile int*)&cons_done = c;             // release ring slots
                for (int w = 0; w < nb; ++w)
                    while (*(volatile int*)&prod_flag[w][buf] < c + 1) nsleep(100);
            }
            asm volatile("bar.sync 1, 128;" ::: "memory");  // chunk c published

            if (c < NCHUNK - 1)
                expand_chunk<CH>(c, buf, nb, tid2, uv_sm, c4s, s4s, o4base);
            else
                expand_chunk<TT - (NCHUNK - 1) * CH>(c, buf, nb, tid2, uv_sm, c4s, s4s, o4base);
        }
        asm volatile("bar.sync 1, 128;" ::: "memory");
        if (tid2 == 0) *(volatile int*)&cons_done = NCHUNK;
    }
}

// --- host-side exact replica of the reference's _xi_inv (double precision) --
static double xi_f(double a, double target)
{
    const double x = (a / 2.0) * (a / 2.0);
    double t0 = 1.0, t1 = a / 2.0;
    double i0 = t0, i1 = t1;
    for (int k = 1; k < 30; ++k) {
        t0 *= x / ((double)k * (double)k);
        t1 *= x / ((double)k * (double)(k + 1));
        i0 += t0;
        i1 += t1;
    }
    return a * i1 / i0 - target;
}

static float compute_kappa_z()
{
    const double target = 15.0 * 0.01;
    double lo = 1e-3, hi = 50.0;
    for (int i = 0; i < 200; ++i) {
        const double mid = 0.5 * (lo + hi);
        if (xi_f(lo, target) * xi_f(mid, target) <= 0.0) hi = mid;
        else lo = mid;
    }
    return (float)(0.5 * (lo + hi));
}

extern "C" void kernel_launch(void* const* d_in, const int* in_sizes, int n_in,
                              void* d_out, int out_size)
{
    const float* inputs = (const float*)d_in[0];  // (B,T,2)
    const float* phi    = (const float*)d_in[4];  // (N,)
    float* out = (float*)d_out;

    const int B = in_sizes[0] / (2 * TT);
    const float kz = compute_kappa_z();

    const int blocks = (B + 3) / 4;               // 4 batches per CTA
    ring_kernel<<<blocks, 256>>>(inputs, phi, out, B, kz, (long long)out_size);
}